// round 11
// baseline (speedup 1.0000x reference)
#include <cuda_runtime.h>
#include <math.h>

#define NN 62
#define BG 512
#define FIN 128
#define HH 64
#define CC 3
#define TRIL ((NN*(NN+1))/2)

// Producer -> consumer handoff (persists across graph replays; contents are
// identical every replay, so concurrent same-value rewrites are benign).
__device__ float g_W1T[FIN*68];  // W1 transposed [k][h], pad cols 64..67 = 0
__device__ float g_A2p[64*68];   // A^2 padded [64][68], zeros outside 62x62
__device__ int   g_flag_w;       // set after g_W1T ready
__device__ int   g_flag_a;       // set after g_A2p ready

// ---------------------------------------------------------------------------
// f32x2 packed helpers
// ---------------------------------------------------------------------------
__device__ __forceinline__ unsigned long long pack2(float x) {
    unsigned long long r;
    asm("mov.b64 %0, {%1, %1};" : "=l"(r) : "f"(x));
    return r;
}
__device__ __forceinline__ unsigned long long packf2(float lo, float hi) {
    unsigned long long r;
    asm("mov.b64 %0, {%1, %2};" : "=l"(r) : "f"(lo), "f"(hi));
    return r;
}
__device__ __forceinline__ void unpack2(unsigned long long v, float& lo, float& hi) {
    asm("mov.b64 {%0, %1}, %2;" : "=f"(lo), "=f"(hi) : "l"(v));
}
__device__ __forceinline__ void fma2(unsigned long long& d,
                                     unsigned long long a, unsigned long long b) {
    asm("fma.rn.f32x2 %0, %1, %2, %0;" : "+l"(d) : "l"(a), "l"(b));
}
__device__ __forceinline__ void lds_v2u64(unsigned long long& a, unsigned long long& b,
                                          const float* p) {
    unsigned sa = (unsigned)__cvta_generic_to_shared(p);
    asm("ld.shared.v2.u64 {%0, %1}, [%2];" : "=l"(a), "=l"(b) : "r"(sa));
}
__device__ __forceinline__ float elem4(float4 v, int i) {
    return (i==0) ? v.x : (i==1) ? v.y : (i==2) ? v.z : v.w;
}

// ---------------------------------------------------------------------------
// Fused single-launch kernel. grid = 513:
//   block 0      : producer (W1 transpose -> g_W1T; A -> A^2 -> g_A2p)
//   blocks 1..512: per-graph fused pipeline, 2n x 8h per-thread tiles
//
// consumer smem aliasing (floats), 17224 total (67.3 KB -> 3 CTAs/SM):
//   region0 [64*132]: Xs during GEMM1; Z row n aliases first 68 floats of
//                     X row n (rows private to 8 consecutive threads -> syncwarp)
//   region1 [128*68]: Wst during GEMM1; A2s[64*68] + part[32*64] after
//   tail    [72]    : pooled[64] + red[8]
// ---------------------------------------------------------------------------
#define XS_F   (64*132)
#define WS_F   (FIN*68)
#define SMEM_FLOATS (XS_F + WS_F + 64 + 8)
#define SMEM_BYTES  (SMEM_FLOATS * 4)

__global__ void __launch_bounds__(256, 3) gcn_fused_kernel(
    const float* __restrict__ x,
    const float* __restrict__ tril,
    const float* __restrict__ W1,
    const float* __restrict__ b1,
    const float* __restrict__ W2,
    const float* __restrict__ b2,
    float* __restrict__ out)
{
    extern __shared__ float sm[];
    int t = threadIdx.x;

    // ===================== PRODUCER (block 0) =====================
    if (blockIdx.x == 0) {
        // 1) W1 transpose first: consumers need it early
        for (int idx = t; idx < FIN*68; idx += 256) {
            int k = idx / 68, h = idx - k*68;
            g_W1T[idx] = (h < HH) ? W1[h*FIN + k] : 0.f;
        }
        __threadfence();
        __syncthreads();
        if (t == 0) atomicExch(&g_flag_w, 1);

        // 2) A -> A^2
        float* Ws   = sm;                 // [62][62]
        float* Af   = sm + NN*NN;         // [62][62]
        float* dinv = sm + 2*NN*NN;       // [62]

        for (int p = t; p < TRIL; p += 256) {
            int i = (int)((sqrtf(8.0f*(float)p + 1.0f) - 1.0f) * 0.5f);
            while ((i+1)*(i+2)/2 <= p) i++;
            while (i*(i+1)/2 > p) i--;
            int j = p - i*(i+1)/2;
            float v = tril[p];
            Ws[i*NN+j] = v;
            Ws[j*NN+i] = v;
        }
        __syncthreads();
        if (t < NN) {
            float s = 0.f;
            for (int j = 0; j < NN; ++j) s += fabsf(Ws[t*NN+j]);
            dinv[t] = (s > 0.f) ? rsqrtf(s) : 0.f;
        }
        __syncthreads();
        for (int p = t; p < NN*NN; p += 256) {
            int i = p / NN, j = p % NN;
            Af[p] = dinv[i] * Ws[p] * dinv[j];
        }
        __syncthreads();
        for (int p = t; p < 64*68; p += 256) {
            int r = p / 68, c = p % 68;
            float s = 0.f;
            if (r < NN && c < NN) {
                for (int m = 0; m < NN; ++m) s += Af[r*NN + m] * Af[m*NN + c];
            }
            g_A2p[p] = s;
        }
        __threadfence();
        __syncthreads();
        if (t == 0) atomicExch(&g_flag_a, 1);
        return;
    }

    // ===================== CONSUMERS =====================
    float* Xs     = sm;                 // [64][132]; Z row n aliases row n
    float* Wst    = Xs + XS_F;          // [128][68] during GEMM1
    float* A2s    = Wst;                // [64][68]  after GEMM1 (aliased)
    float* part   = Wst + 64*68;        // [32][64]  after GEMM2 (aliased)
    float* pooled = sm + XS_F + WS_F;   // [64]
    float* red    = pooled + HH;        // [8]

    int g = blockIdx.x - 1;
    const float* xg = x + (size_t)g * NN * FIN;

    // ---- stage X (coalesced float4) ----
    for (int e = t; e < NN*32; e += 256) {
        int row = e >> 5, c4 = e & 31;
        float4 v = *(const float4*)(xg + row*FIN + 4*c4);
        *(float4*)(Xs + row*132 + 4*c4) = v;
    }
    // rows 62,63: cols 0..127 read in GEMM1 -> zero them
    for (int p = t; p < 2*FIN; p += 256) Xs[62*132 + (p>>7)*132 + (p&127)] = 0.f;

    // ---- wait for transposed W1, then straight float4 copy ----
    if (t == 0) {
        while (atomicAdd(&g_flag_w, 0) == 0) __nanosleep(32);
        __threadfence();
    }
    __syncthreads();
    for (int e = t; e < (FIN*68)/4; e += 256)
        *(float4*)(Wst + 4*e) = *(const float4*)(g_W1T + 4*e);
    __syncthreads();

    int hs = t & 7;          // h0 = 8*hs : 8 h-features per thread
    int n2 = t >> 3;         // rows r0 = 2*n2, r1 = 2*n2+1
    int h0 = 8*hs;
    int r0 = 2*n2, r1 = 2*n2 + 1;

    // ---- GEMM1: Z = X @ W1^T  (2 nodes x 8 h per thread, f32x2) ----
    {
        unsigned long long a0[4], a1[4];
        #pragma unroll
        for (int j = 0; j < 4; ++j) { a0[j] = 0ull; a1[j] = 0ull; }

        const float* x0 = Xs + r0*132;
        const float* x1 = Xs + r1*132;

        #pragma unroll 4
        for (int k = 0; k < FIN; k += 4) {
            float4 xa = *(const float4*)(x0 + k);
            float4 xb = *(const float4*)(x1 + k);
            #pragma unroll
            for (int kk = 0; kk < 4; ++kk) {
                unsigned long long w0, w1, w2, w3;
                lds_v2u64(w0, w1, Wst + (k+kk)*68 + h0);
                lds_v2u64(w2, w3, Wst + (k+kk)*68 + h0 + 4);
                unsigned long long pa = pack2(elem4(xa, kk));
                unsigned long long pb = pack2(elem4(xb, kk));
                fma2(a0[0], pa, w0); fma2(a0[1], pa, w1);
                fma2(a0[2], pa, w2); fma2(a0[3], pa, w3);
                fma2(a1[0], pb, w0); fma2(a1[1], pb, w1);
                fma2(a1[2], pb, w2); fma2(a1[3], pb, w3);
            }
        }
        // Z row r aliases X row r (first 68 floats). X rows r0,r1 are read
        // only by the 8 consecutive threads sharing n2 (same warp).
        __syncwarp();
        { ulonglong2 v; v.x = a0[0]; v.y = a0[1];
          *(ulonglong2*)(Xs + r0*132 + h0) = v; }
        { ulonglong2 v; v.x = a0[2]; v.y = a0[3];
          *(ulonglong2*)(Xs + r0*132 + h0 + 4) = v; }
        { ulonglong2 v; v.x = a1[0]; v.y = a1[1];
          *(ulonglong2*)(Xs + r1*132 + h0) = v; }
        { ulonglong2 v; v.x = a1[2]; v.y = a1[3];
          *(ulonglong2*)(Xs + r1*132 + h0 + 4) = v; }
    }

    // ---- wait for A^2 (producer done long ago), copy over Wst ----
    if (t == 0) {
        while (atomicAdd(&g_flag_a, 0) == 0) __nanosleep(64);
        __threadfence();
    }
    __syncthreads();   // all GEMM1 Wst/Xs reads done + flag observed
    for (int e = t; e < (64*68)/4; e += 256)
        *(float4*)(A2s + 4*e) = *(const float4*)(g_A2p + 4*e);
    __syncthreads();

    // ---- GEMM2: Y = A2 @ Z + b1, relu, pool ----
    unsigned long long a0[4], a1[4];
    {
        float4 bv0 = *(const float4*)(b1 + h0);
        float4 bv1 = *(const float4*)(b1 + h0 + 4);
        a0[0] = packf2(bv0.x, bv0.y); a0[1] = packf2(bv0.z, bv0.w);
        a0[2] = packf2(bv1.x, bv1.y); a0[3] = packf2(bv1.z, bv1.w);
        #pragma unroll
        for (int j = 0; j < 4; ++j) a1[j] = a0[j];

        const float* ar0 = A2s + r0*68;
        const float* ar1 = A2s + r1*68;

        #pragma unroll 4
        for (int m = 0; m < 64; m += 4) {
            float4 va = *(const float4*)(ar0 + m);
            float4 vb = *(const float4*)(ar1 + m);
            #pragma unroll
            for (int mm = 0; mm < 4; ++mm) {
                unsigned long long z0, z1, z2, z3;
                lds_v2u64(z0, z1, Xs + (m+mm)*132 + h0);
                lds_v2u64(z2, z3, Xs + (m+mm)*132 + h0 + 4);
                unsigned long long pa = pack2(elem4(va, mm));
                unsigned long long pb = pack2(elem4(vb, mm));
                fma2(a0[0], pa, z0); fma2(a0[1], pa, z1);
                fma2(a0[2], pa, z2); fma2(a0[3], pa, z3);
                fma2(a1[0], pb, z0); fma2(a1[1], pb, z1);
                fma2(a1[2], pb, z2); fma2(a1[3], pb, z3);
            }
        }
    }

    // relu + pool over this thread's (<=2) valid nodes, 8 h each
    {
        float p[8];
        #pragma unroll
        for (int j = 0; j < 8; ++j) p[j] = 0.f;
        if (r0 < NN) {
            #pragma unroll
            for (int j = 0; j < 4; ++j) {
                float lo, hi; unpack2(a0[j], lo, hi);
                p[2*j]   += fmaxf(lo, 0.f);
                p[2*j+1] += fmaxf(hi, 0.f);
            }
        }
        if (r1 < NN) {
            #pragma unroll
            for (int j = 0; j < 4; ++j) {
                float lo, hi; unpack2(a1[j], lo, hi);
                p[2*j]   += fmaxf(lo, 0.f);
                p[2*j+1] += fmaxf(hi, 0.f);
            }
        }
        *(float4*)(part + n2*64 + h0)     = make_float4(p[0], p[1], p[2], p[3]);
        *(float4*)(part + n2*64 + h0 + 4) = make_float4(p[4], p[5], p[6], p[7]);
    }
    __syncthreads();

    if (t < HH) {
        float s = 0.f;
        #pragma unroll
        for (int gg = 0; gg < 32; ++gg) s += part[gg*64 + t];
        pooled[t] = s;
    }
    __syncthreads();

    // ---- logits = pooled @ W2^T + b2 ----
    if (t < CC) {
        float s = b2[t];
        const float* w2r = W2 + t*HH;
        #pragma unroll 8
        for (int hh = 0; hh < HH; ++hh) s = fmaf(w2r[hh], pooled[hh], s);
        red[t] = s;
    }
    __syncthreads();

    // ---- outputs ----
    if (t < HH) out[(size_t)g*HH + t] = pooled[t];
    if (t == 0) {
        float mx = fmaxf(red[0], fmaxf(red[1], red[2]));
        float sum = expf(red[0]-mx) + expf(red[1]-mx) + expf(red[2]-mx);
        red[4] = mx + logf(sum);
    }
    __syncthreads();
    if (t < CC)
        out[(size_t)BG*HH + (size_t)g*CC + t] = red[t] - red[4];
}

// ---------------------------------------------------------------------------
extern "C" void kernel_launch(void* const* d_in, const int* in_sizes, int n_in,
                              void* d_out, int out_size) {
    const float* x    = (const float*)d_in[0];
    const float* tril = (const float*)d_in[1];
    const float* W1   = (const float*)d_in[2];
    const float* b1   = (const float*)d_in[3];
    const float* W2   = (const float*)d_in[4];
    const float* b2   = (const float*)d_in[5];
    float* out = (float*)d_out;

    cudaFuncSetAttribute(gcn_fused_kernel,
                         cudaFuncAttributeMaxDynamicSharedMemorySize, SMEM_BYTES);

    gcn_fused_kernel<<<BG + 1, 256, SMEM_BYTES>>>(x, tril, W1, b1, W2, b2, out);
}

// round 15
// speedup vs baseline: 1.9704x; 1.9704x over previous
#include <cuda_runtime.h>
#include <math.h>

#define NN 62
#define BG 512
#define FIN 128
#define HH 64
#define CC 3
#define TRIL ((NN*(NN+1))/2)

// Producer -> consumer handoff (persists across graph replays; contents are
// identical every replay, so concurrent same-value rewrites are benign).
__device__ float g_W1T[FIN*68];  // W1 transposed [k][h], pad cols 64..67 = 0
__device__ float g_A2p[64*68];   // A^2 padded [64][68], zeros outside 62x62
__device__ int   g_flag_w;       // set after g_W1T ready
__device__ int   g_flag_a;       // set after g_A2p ready

// ---------------------------------------------------------------------------
// f32x2 packed helpers
// ---------------------------------------------------------------------------
__device__ __forceinline__ unsigned long long pack2(float x) {
    unsigned long long r;
    asm("mov.b64 %0, {%1, %1};" : "=l"(r) : "f"(x));
    return r;
}
__device__ __forceinline__ unsigned long long packf2(float lo, float hi) {
    unsigned long long r;
    asm("mov.b64 %0, {%1, %2};" : "=l"(r) : "f"(lo), "f"(hi));
    return r;
}
__device__ __forceinline__ void unpack2(unsigned long long v, float& lo, float& hi) {
    asm("mov.b64 {%0, %1}, %2;" : "=f"(lo), "=f"(hi) : "l"(v));
}
__device__ __forceinline__ void fma2(unsigned long long& d,
                                     unsigned long long a, unsigned long long b) {
    asm("fma.rn.f32x2 %0, %1, %2, %0;" : "+l"(d) : "l"(a), "l"(b));
}
__device__ __forceinline__ void lds_v2u64(unsigned long long& a, unsigned long long& b,
                                          const float* p) {
    unsigned sa = (unsigned)__cvta_generic_to_shared(p);
    asm("ld.shared.v2.u64 {%0, %1}, [%2];" : "=l"(a), "=l"(b) : "r"(sa));
}

// ---------------------------------------------------------------------------
// Fused single-launch kernel. grid = 513:
//   block 0      : producer (W1 transpose -> g_W1T; A -> A^2 -> g_A2p)
//   blocks 1..512: per-graph fused pipeline, 4n x 4h per-thread tiles with
//                  load batching at the top of each 4-k block (MLP >= 8)
//
// consumer smem aliasing (floats), 17224 total (67.3 KB -> 3 CTAs/SM):
//   region0 [64*132]: Xs during GEMM1; Z row n aliases first 68 floats of
//                     X row n (rows private to 16 threads of one warp)
//   region1 [128*68]: Wst during GEMM1; A2s[64*68] + part[16*64] after
//   tail    [72]    : pooled[64] + red[8]
// ---------------------------------------------------------------------------
#define XS_F   (64*132)
#define WS_F   (FIN*68)
#define SMEM_FLOATS (XS_F + WS_F + 64 + 8)
#define SMEM_BYTES  (SMEM_FLOATS * 4)

__global__ void __launch_bounds__(256, 3) gcn_fused_kernel(
    const float* __restrict__ x,
    const float* __restrict__ tril,
    const float* __restrict__ W1,
    const float* __restrict__ b1,
    const float* __restrict__ W2,
    const float* __restrict__ b2,
    float* __restrict__ out)
{
    extern __shared__ float sm[];
    int t = threadIdx.x;

    // ===================== PRODUCER (block 0) =====================
    if (blockIdx.x == 0) {
        // 1) W1 transpose first: consumers need it early
        for (int idx = t; idx < FIN*68; idx += 256) {
            int k = idx / 68, h = idx - k*68;
            g_W1T[idx] = (h < HH) ? W1[h*FIN + k] : 0.f;
        }
        __threadfence();
        __syncthreads();
        if (t == 0) atomicExch(&g_flag_w, 1);

        // 2) A -> A^2
        float* Ws   = sm;                 // [62][62]
        float* Af   = sm + NN*NN;         // [62][62]
        float* dinv = sm + 2*NN*NN;       // [62]

        for (int p = t; p < TRIL; p += 256) {
            int i = (int)((sqrtf(8.0f*(float)p + 1.0f) - 1.0f) * 0.5f);
            while ((i+1)*(i+2)/2 <= p) i++;
            while (i*(i+1)/2 > p) i--;
            int j = p - i*(i+1)/2;
            float v = tril[p];
            Ws[i*NN+j] = v;
            Ws[j*NN+i] = v;
        }
        __syncthreads();
        if (t < NN) {
            float s = 0.f;
            for (int j = 0; j < NN; ++j) s += fabsf(Ws[t*NN+j]);
            dinv[t] = (s > 0.f) ? rsqrtf(s) : 0.f;
        }
        __syncthreads();
        for (int p = t; p < NN*NN; p += 256) {
            int i = p / NN, j = p % NN;
            Af[p] = dinv[i] * Ws[p] * dinv[j];
        }
        __syncthreads();
        for (int p = t; p < 64*68; p += 256) {
            int r = p / 68, c = p % 68;
            float s = 0.f;
            if (r < NN && c < NN) {
                for (int m = 0; m < NN; ++m) s += Af[r*NN + m] * Af[m*NN + c];
            }
            g_A2p[p] = s;
        }
        __threadfence();
        __syncthreads();
        if (t == 0) atomicExch(&g_flag_a, 1);
        return;
    }

    // ===================== CONSUMERS =====================
    float* Xs     = sm;                 // [64][132]; Z row n aliases row n
    float* Wst    = Xs + XS_F;          // [128][68] during GEMM1
    float* A2s    = Wst;                // [64][68]  after GEMM1 (aliased)
    float* part   = Wst + 64*68;        // [16][64]  after GEMM2 (aliased)
    float* pooled = sm + XS_F + WS_F;   // [64]
    float* red    = pooled + HH;        // [8]

    int g = blockIdx.x - 1;
    const float* xg = x + (size_t)g * NN * FIN;

    // ---- stage X (coalesced float4); overlaps producer's W1 transpose ----
    for (int e = t; e < NN*32; e += 256) {
        int row = e >> 5, c4 = e & 31;
        float4 v = *(const float4*)(xg + row*FIN + 4*c4);
        *(float4*)(Xs + row*132 + 4*c4) = v;
    }
    // rows 62,63: cols 0..127 read in GEMM1 -> zero them
    for (int p = t; p < 2*FIN; p += 256) Xs[62*132 + (p>>7)*132 + (p&127)] = 0.f;

    // ---- wait for transposed W1, then straight conflict-free float4 copy ----
    if (t == 0) {
        while (atomicAdd(&g_flag_w, 0) == 0) __nanosleep(32);
        __threadfence();
    }
    __syncthreads();
    for (int e = t; e < (FIN*68)/4; e += 256)
        *(float4*)(Wst + 4*e) = *(const float4*)(g_W1T + 4*e);
    __syncthreads();

    int hg = t & 15;        // h0 = 4*hg
    int ng = t >> 4;        // nodes 4*ng .. 4*ng+3
    int h0 = 4*hg;

    // ---- GEMM1: Z = X @ W1^T  (4 nodes x 4 h per thread, f32x2) ----
    {
        unsigned long long acc[4][2];
        #pragma unroll
        for (int j = 0; j < 4; ++j) { acc[j][0] = 0ull; acc[j][1] = 0ull; }

        const float* xr0 = Xs + (4*ng+0)*132;
        const float* xr1 = Xs + (4*ng+1)*132;
        const float* xr2 = Xs + (4*ng+2)*132;
        const float* xr3 = Xs + (4*ng+3)*132;

        #pragma unroll 4
        for (int k = 0; k < FIN; k += 4) {
            // batch all 8 loads up front -> MLP >= 8
            unsigned long long w[4][2];
            #pragma unroll
            for (int kk = 0; kk < 4; ++kk)
                lds_v2u64(w[kk][0], w[kk][1], Wst + (k+kk)*68 + h0);
            float4 xv0 = *(const float4*)(xr0 + k);
            float4 xv1 = *(const float4*)(xr1 + k);
            float4 xv2 = *(const float4*)(xr2 + k);
            float4 xv3 = *(const float4*)(xr3 + k);
            #pragma unroll
            for (int kk = 0; kk < 4; ++kk) {
                float f0 = (kk==0)?xv0.x:(kk==1)?xv0.y:(kk==2)?xv0.z:xv0.w;
                float f1 = (kk==0)?xv1.x:(kk==1)?xv1.y:(kk==2)?xv1.z:xv1.w;
                float f2 = (kk==0)?xv2.x:(kk==1)?xv2.y:(kk==2)?xv2.z:xv2.w;
                float f3 = (kk==0)?xv3.x:(kk==1)?xv3.y:(kk==2)?xv3.z:xv3.w;
                unsigned long long p0 = pack2(f0), p1 = pack2(f1);
                unsigned long long p2 = pack2(f2), p3 = pack2(f3);
                fma2(acc[0][0], p0, w[kk][0]); fma2(acc[0][1], p0, w[kk][1]);
                fma2(acc[1][0], p1, w[kk][0]); fma2(acc[1][1], p1, w[kk][1]);
                fma2(acc[2][0], p2, w[kk][0]); fma2(acc[2][1], p2, w[kk][1]);
                fma2(acc[3][0], p3, w[kk][0]); fma2(acc[3][1], p3, w[kk][1]);
            }
        }
        // Z row n aliases X row n (first 68 floats). X rows 4ng..4ng+3 are
        // read only by the 16 lanes sharing ng (same warp) -> warp-sync guard.
        __syncwarp();
        #pragma unroll
        for (int j = 0; j < 4; ++j) {
            ulonglong2 v; v.x = acc[j][0]; v.y = acc[j][1];
            *(ulonglong2*)(Xs + (4*ng+j)*132 + h0) = v;
        }
    }

    // ---- wait for A^2 (producer done long ago), copy over Wst ----
    if (t == 0) {
        while (atomicAdd(&g_flag_a, 0) == 0) __nanosleep(64);
        __threadfence();
    }
    __syncthreads();   // all GEMM1 Wst/Xs reads done + flag observed
    for (int e = t; e < (64*68)/4; e += 256)
        *(float4*)(A2s + 4*e) = *(const float4*)(g_A2p + 4*e);
    __syncthreads();

    // ---- GEMM2: Y = A2 @ Z + b1, relu, pool ----
    float4 b1v = *(const float4*)(b1 + h0);
    unsigned long long acc2[4][2];
    {
        unsigned long long bp0 = packf2(b1v.x, b1v.y);
        unsigned long long bp1 = packf2(b1v.z, b1v.w);
        #pragma unroll
        for (int j = 0; j < 4; ++j) { acc2[j][0] = bp0; acc2[j][1] = bp1; }

        const float* ar0 = A2s + (4*ng+0)*68;
        const float* ar1 = A2s + (4*ng+1)*68;
        const float* ar2 = A2s + (4*ng+2)*68;
        const float* ar3 = A2s + (4*ng+3)*68;

        #pragma unroll 4
        for (int m = 0; m < 64; m += 4) {
            unsigned long long z[4][2];
            #pragma unroll
            for (int mm = 0; mm < 4; ++mm)
                lds_v2u64(z[mm][0], z[mm][1], Xs + (m+mm)*132 + h0);
            float4 av0 = *(const float4*)(ar0 + m);
            float4 av1 = *(const float4*)(ar1 + m);
            float4 av2 = *(const float4*)(ar2 + m);
            float4 av3 = *(const float4*)(ar3 + m);
            #pragma unroll
            for (int mm = 0; mm < 4; ++mm) {
                float f0 = (mm==0)?av0.x:(mm==1)?av0.y:(mm==2)?av0.z:av0.w;
                float f1 = (mm==0)?av1.x:(mm==1)?av1.y:(mm==2)?av1.z:av1.w;
                float f2 = (mm==0)?av2.x:(mm==1)?av2.y:(mm==2)?av2.z:av2.w;
                float f3 = (mm==0)?av3.x:(mm==1)?av3.y:(mm==2)?av3.z:av3.w;
                unsigned long long p0 = pack2(f0), p1 = pack2(f1);
                unsigned long long p2 = pack2(f2), p3 = pack2(f3);
                fma2(acc2[0][0], p0, z[mm][0]); fma2(acc2[0][1], p0, z[mm][1]);
                fma2(acc2[1][0], p1, z[mm][0]); fma2(acc2[1][1], p1, z[mm][1]);
                fma2(acc2[2][0], p2, z[mm][0]); fma2(acc2[2][1], p2, z[mm][1]);
                fma2(acc2[3][0], p3, z[mm][0]); fma2(acc2[3][1], p3, z[mm][1]);
            }
        }
    }

    // relu + pool (mask nodes >= 62)
    {
        float ps0 = 0.f, ps1 = 0.f, ps2 = 0.f, ps3 = 0.f;
        #pragma unroll
        for (int j = 0; j < 4; ++j) {
            if (4*ng + j < NN) {
                float y0, y1, y2, y3;
                unpack2(acc2[j][0], y0, y1);
                unpack2(acc2[j][1], y2, y3);
                ps0 += fmaxf(y0, 0.f);
                ps1 += fmaxf(y1, 0.f);
                ps2 += fmaxf(y2, 0.f);
                ps3 += fmaxf(y3, 0.f);
            }
        }
        *(float4*)(part + ng*64 + h0) = make_float4(ps0, ps1, ps2, ps3);
    }
    __syncthreads();

    if (t < HH) {
        float s = 0.f;
        #pragma unroll
        for (int gg = 0; gg < 16; ++gg) s += part[gg*64 + t];
        pooled[t] = s;
    }
    __syncthreads();

    // ---- logits = pooled @ W2^T + b2 ----
    if (t < CC) {
        float s = b2[t];
        const float* w2r = W2 + t*HH;
        #pragma unroll 8
        for (int hh = 0; hh < HH; ++hh) s = fmaf(w2r[hh], pooled[hh], s);
        red[t] = s;
    }
    __syncthreads();

    // ---- outputs ----
    if (t < HH) out[(size_t)g*HH + t] = pooled[t];
    if (t == 0) {
        float mx = fmaxf(red[0], fmaxf(red[1], red[2]));
        float sum = expf(red[0]-mx) + expf(red[1]-mx) + expf(red[2]-mx);
        red[4] = mx + logf(sum);
    }
    __syncthreads();
    if (t < CC)
        out[(size_t)BG*HH + (size_t)g*CC + t] = red[t] - red[4];
}

// ---------------------------------------------------------------------------
extern "C" void kernel_launch(void* const* d_in, const int* in_sizes, int n_in,
                              void* d_out, int out_size) {
    const float* x    = (const float*)d_in[0];
    const float* tril = (const float*)d_in[1];
    const float* W1   = (const float*)d_in[2];
    const float* b1   = (const float*)d_in[3];
    const float* W2   = (const float*)d_in[4];
    const float* b2   = (const float*)d_in[5];
    float* out = (float*)d_out;

    cudaFuncSetAttribute(gcn_fused_kernel,
                         cudaFuncAttributeMaxDynamicSharedMemorySize, SMEM_BYTES);

    gcn_fused_kernel<<<BG + 1, 256, SMEM_BYTES>>>(x, tril, W1, b1, W2, b2, out);
}